// round 16
// baseline (speedup 1.0000x reference)
#include <cuda_runtime.h>

// SNN forward scan: rows = B*N = 65536 independent length-512 recurrences.
// R16 = R9 read pipeline (one warp/block, 32 rows, CHUNK=128 -> 512B-run
// coalesced double-buffered cp.async) + 1KB WRITE RUNS: spikes are packed
// 2-per-uint32 (fp32 high halves, 0x3F80/0) into a smem output buffer and
// flushed every 2 chunks, so each row's store is one contiguous 1 KB DRAM
// run (expansion = two integer shifts per float4; no cvt).
// Refractory window as multiplicative mask: ic = x*(1-s[t-1])*(1-s[t-2]).

#define T_STEPS 512
#define CHUNK   128
#define ROWS    32                 // threads per block == rows per block
#define NCHUNK  (T_STEPS / CHUNK)  // 4
#define ISTRIDE 132                // input smem row stride (floats); conflict-free
#define OSTRIDE 134                // output smem row stride (uint32); even, low-conflict
#define LDI     32                 // cp.async iterations per stage (one 512B row-run)

__device__ __forceinline__ void cp_async16(float* smem_dst, const float* gmem_src) {
    unsigned saddr = (unsigned)__cvta_generic_to_shared(smem_dst);
    asm volatile("cp.async.cg.shared.global [%0], [%1], 16;\n"
                 :: "r"(saddr), "l"(gmem_src));
}

__global__ __launch_bounds__(ROWS) void snn_fwd_kernel(
    const float* __restrict__ x,
    const float* __restrict__ beta,
    const float* __restrict__ p,
    const float* __restrict__ b,
    float* __restrict__ out,
    int N)
{
    __shared__ float    tile[2][ROWS * ISTRIDE];   // 33.8 KB
    __shared__ unsigned obuf[ROWS * OSTRIDE];      // 17.2 KB (256 packed steps/row)

    const int tid = threadIdx.x;
    const size_t row_base = (size_t)blockIdx.x * ROWS;
    const int n = (int)((row_base + tid) % (size_t)N);

    // clamped effective per-neuron params
    const float beta_c = fminf(fmaxf(beta[n], 0.001f), 0.999f);
    const float p_c    = fminf(fabsf(p[n]), 0.999f);
    const float b_c    = fminf(fmaxf(fabsf(b[n]), 0.001f), 1.0f);

    // recurrence state
    float mem = 0.0f, a = 0.0f, vth = 1.0f;
    float m1 = 1.0f, m2 = 1.0f;   // 1 - s(t-1), 1 - s(t-2)

    // preload chunks 0 and 1 (iteration k = row k's contiguous 512B run)
    #pragma unroll
    for (int t = 0; t < 2; ++t) {
        const float* base = x + row_base * T_STEPS + t * CHUNK;
        #pragma unroll
        for (int k = 0; k < LDI; ++k)
            cp_async16(&tile[t][k * ISTRIDE + tid * 4], base + k * T_STEPS + tid * 4);
        asm volatile("cp.async.commit_group;\n");
    }

    #pragma unroll
    for (int c = 0; c < NCHUNK; ++c) {
        float* buf = tile[c & 1];

        if (c + 1 < NCHUNK) asm volatile("cp.async.wait_group 1;\n");
        else                asm volatile("cp.async.wait_group 0;\n");
        __syncwarp();

        // compute chunk c: thread owns row tid; pack spike pairs into obuf.
        // word j of the 256-step pair-window holds steps 2j (lo16) and 2j+1
        // (hi16) as fp32 high halves: 0x3F80 -> 1.0f, 0x0000 -> 0.0f.
        {
            float* rowp = buf + tid * ISTRIDE;
            unsigned* orow = obuf + tid * OSTRIDE + (c & 1) * 64;
            #pragma unroll 8
            for (int i = 0; i < CHUNK / 4; ++i) {
                float4 xv = *reinterpret_cast<float4*>(rowp + i * 4);
                unsigned w0, w1;
                {
                    const float ic = (xv.x * m2) * m1;
                    const float nm = fmaf(mem, beta_c, ic);
                    const bool  sp = nm > vth;
                    mem = sp ? 0.0f : nm;
                    a   = fmaf(p_c, a, sp ? 1.0f : 0.0f);
                    vth = fmaf(b_c, a, 1.0f);
                    m2 = m1; m1 = sp ? 0.0f : 1.0f;
                    w0 = sp ? 0x3F80u : 0u;
                }
                {
                    const float ic = (xv.y * m2) * m1;
                    const float nm = fmaf(mem, beta_c, ic);
                    const bool  sp = nm > vth;
                    mem = sp ? 0.0f : nm;
                    a   = fmaf(p_c, a, sp ? 1.0f : 0.0f);
                    vth = fmaf(b_c, a, 1.0f);
                    m2 = m1; m1 = sp ? 0.0f : 1.0f;
                    w0 |= sp ? 0x3F800000u : 0u;
                }
                {
                    const float ic = (xv.z * m2) * m1;
                    const float nm = fmaf(mem, beta_c, ic);
                    const bool  sp = nm > vth;
                    mem = sp ? 0.0f : nm;
                    a   = fmaf(p_c, a, sp ? 1.0f : 0.0f);
                    vth = fmaf(b_c, a, 1.0f);
                    m2 = m1; m1 = sp ? 0.0f : 1.0f;
                    w1 = sp ? 0x3F80u : 0u;
                }
                {
                    const float ic = (xv.w * m2) * m1;
                    const float nm = fmaf(mem, beta_c, ic);
                    const bool  sp = nm > vth;
                    mem = sp ? 0.0f : nm;
                    a   = fmaf(p_c, a, sp ? 1.0f : 0.0f);
                    vth = fmaf(b_c, a, 1.0f);
                    m2 = m1; m1 = sp ? 0.0f : 1.0f;
                    w1 |= sp ? 0x3F800000u : 0u;
                }
                uint2 wp; wp.x = w0; wp.y = w1;
                *reinterpret_cast<uint2*>(orow + i * 2) = wp;
            }
        }
        __syncwarp();   // packed words visible warp-wide

        // flush every 2 chunks: each row emits one contiguous 1 KB run
        if (c & 1) {
            const int pair = c >> 1;
            float* obase = out + row_base * T_STEPS + (size_t)pair * 256;
            #pragma unroll 8
            for (int it = 0; it < 64; ++it) {
                const int r = it >> 1, h = it & 1;   // h=0,1: row r's two 512B halves
                const uint2 w = *reinterpret_cast<const uint2*>(
                    obuf + r * OSTRIDE + h * 64 + tid * 2);
                float4 v;
                v.x = __uint_as_float(w.x << 16);
                v.y = __uint_as_float(w.x & 0xFFFF0000u);
                v.z = __uint_as_float(w.y << 16);
                v.w = __uint_as_float(w.y & 0xFFFF0000u);
                __stcs(reinterpret_cast<float4*>(
                    obase + (size_t)r * T_STEPS + h * CHUNK + tid * 4), v);
            }
            __syncwarp();   // obuf reusable before chunk c+1's compute
        }

        // prefetch chunk c+2 into the input buffer just consumed
        if (c + 2 < NCHUNK) {
            const float* base = x + row_base * T_STEPS + (c + 2) * CHUNK;
            #pragma unroll
            for (int k = 0; k < LDI; ++k)
                cp_async16(buf + k * ISTRIDE + tid * 4, base + k * T_STEPS + tid * 4);
            asm volatile("cp.async.commit_group;\n");
        }
    }
}

extern "C" void kernel_launch(void* const* d_in, const int* in_sizes, int n_in,
                              void* d_out, int out_size)
{
    const float* x    = (const float*)d_in[0];
    const float* beta = (const float*)d_in[1];
    const float* p    = (const float*)d_in[2];
    const float* b    = (const float*)d_in[3];
    float* out        = (float*)d_out;

    const int N    = in_sizes[1];               // 1024
    const int rows = in_sizes[0] / T_STEPS;     // B*N = 65536

    const int blocks = rows / ROWS;             // 2048
    snn_fwd_kernel<<<blocks, ROWS>>>(x, beta, p, b, out, N);
}

// round 17
// speedup vs baseline: 1.2477x; 1.2477x over previous
#include <cuda_runtime.h>

// SNN forward scan: rows = B*N = 65536 independent length-512 recurrences.
// FINAL (= R9, best of 16 rounds: 49.2us, ~5.45 TB/s effective mixed R/W).
// One warp per block, 32 rows. CHUNK=128 timesteps -> every cooperative
// load/store iteration moves one row's full contiguous 512 B run (one DRAM
// page burst; the measured optimum: shorter runs lose to R/W interleave
// tax, longer runs cost residency/pipeline/lanes). Double-buffered cp.async,
// issue-then-wait, 4 stages; ~6 blocks/SM. Refractory window as
// multiplicative mask: ic(t) = x(t) * (1-s(t-1)) * (1-s(t-2)).

#define T_STEPS 512
#define CHUNK   128
#define ROWS    32                // threads per block == rows per block
#define NCHUNK  (T_STEPS / CHUNK) // 4
#define STRIDE  132               // padded smem row stride (floats); 132%32=4 -> conflict-free
#define NBUF    2
#define LDI     32                // coop iterations per stage (one 512B row-run each)

__device__ __forceinline__ void cp_async16(float* smem_dst, const float* gmem_src) {
    unsigned saddr = (unsigned)__cvta_generic_to_shared(smem_dst);
    asm volatile("cp.async.cg.shared.global [%0], [%1], 16;\n"
                 :: "r"(saddr), "l"(gmem_src));
}

__global__ __launch_bounds__(ROWS) void snn_fwd_kernel(
    const float* __restrict__ x,
    const float* __restrict__ beta,
    const float* __restrict__ p,
    const float* __restrict__ b,
    float* __restrict__ out,
    int N)
{
    __shared__ float tile[NBUF][ROWS * STRIDE];

    const int tid = threadIdx.x;
    const size_t row_base = (size_t)blockIdx.x * ROWS;
    const int n = (int)((row_base + tid) % (size_t)N);

    // clamped effective per-neuron params
    const float beta_c = fminf(fmaxf(beta[n], 0.001f), 0.999f);
    const float p_c    = fminf(fabsf(p[n]), 0.999f);
    const float b_c    = fminf(fmaxf(fabsf(b[n]), 0.001f), 1.0f);

    // recurrence state
    float mem = 0.0f, a = 0.0f, vth = 1.0f;
    float m1 = 1.0f, m2 = 1.0f;   // 1 - s(t-1), 1 - s(t-2)

    // cooperative addressing: iteration k moves row k's full 512B chunk;
    // the 32 lanes cover byte offsets tid*16 .. tid*16+15 -> one contiguous
    // 512B run per iteration (single-page DRAM burst).

    // preload chunk 0
    #pragma unroll
    for (int k = 0; k < LDI; ++k) {
        cp_async16(&tile[0][k * STRIDE + tid * 4],
                   x + (row_base + k) * T_STEPS + tid * 4);
    }
    asm volatile("cp.async.commit_group;\n");

    for (int c = 0; c < NCHUNK; ++c) {
        const int buf = c & 1;

        // issue next stage first (keeps a 16KB group in flight during wait)
        if (c + 1 < NCHUNK) {
            #pragma unroll
            for (int k = 0; k < LDI; ++k) {
                cp_async16(&tile[buf ^ 1][k * STRIDE + tid * 4],
                           x + (row_base + k) * T_STEPS + (c + 1) * CHUNK + tid * 4);
            }
            asm volatile("cp.async.commit_group;\n");
            asm volatile("cp.async.wait_group 1;\n");   // stage c arrived
        } else {
            asm volatile("cp.async.wait_group 0;\n");
        }
        __syncwarp();

        // compute: each thread owns one smem row; overwrite x with spikes
        float* rowp = &tile[buf][tid * STRIDE];
        #pragma unroll 8
        for (int i = 0; i < CHUNK / 4; ++i) {
            float4 xv = *reinterpret_cast<float4*>(rowp + i * 4);
            float4 ov;
            #pragma unroll
            for (int k = 0; k < 4; ++k) {
                const float xt = (k == 0) ? xv.x : (k == 1) ? xv.y
                               : (k == 2) ? xv.z : xv.w;
                const float ic = xt * (m1 * m2);          // refractory mask
                const float nm = fmaf(mem, beta_c, ic);   // leaky integrate
                const float ns = (nm > vth) ? 0.0f : 1.0f;
                const float s  = 1.0f - ns;
                mem = nm * ns;                            // reset-to-zero
                a   = fmaf(p_c, a, s);                    // adaptation
                vth = fmaf(b_c, a, 1.0f);
                m2 = m1; m1 = ns;
                if (k == 0) ov.x = s; else if (k == 1) ov.y = s;
                else if (k == 2) ov.z = s; else ov.w = s;
            }
            *reinterpret_cast<float4*>(rowp + i * 4) = ov;
        }
        __syncwarp();   // spikes visible warp-wide for cooperative store

        // cooperative store: one contiguous 512B run per iteration
        #pragma unroll
        for (int k = 0; k < LDI; ++k) {
            const float4 v = *reinterpret_cast<const float4*>(
                &tile[buf][k * STRIDE + tid * 4]);
            __stcs(reinterpret_cast<float4*>(
                out + (row_base + k) * T_STEPS + c * CHUNK + tid * 4), v);
        }
        // buffer reuse: stage c+2's prefetch (issued at top of c+1) targets
        // this buffer, and is program-ordered after this store loop.
    }
}

extern "C" void kernel_launch(void* const* d_in, const int* in_sizes, int n_in,
                              void* d_out, int out_size)
{
    const float* x    = (const float*)d_in[0];
    const float* beta = (const float*)d_in[1];
    const float* p    = (const float*)d_in[2];
    const float* b    = (const float*)d_in[3];
    float* out        = (float*)d_out;

    const int N    = in_sizes[1];               // 1024
    const int rows = in_sizes[0] / T_STEPS;     // B*N = 65536

    const int blocks = rows / ROWS;             // 2048
    snn_fwd_kernel<<<blocks, ROWS>>>(x, beta, p, b, out, N);
}